// round 15
// baseline (speedup 1.0000x reference)
#include <cuda_runtime.h>

// Fixed problem shape
#define BB 256
#define TT 4096
#define CC 16
#define HH 20
#define GG 60
#define K  16
#define NC (TT / K)   // 256 chunks

typedef unsigned long long u64;

__device__ __forceinline__ u64 pack2(float a, float b) {
    u64 r; asm("mov.b64 %0,{%1,%2};" : "=l"(r) : "f"(a), "f"(b)); return r;
}
__device__ __forceinline__ void unpack2(u64 v, float& a, float& b) {
    asm("mov.b64 {%0,%1},%2;" : "=f"(a), "=f"(b) : "l"(v));
}
__device__ __forceinline__ void fma2(u64& d, u64 a, u64 b) {
    asm("fma.rn.f32x2 %0,%1,%2,%0;" : "+l"(d) : "l"(a), "l"(b));
}
__device__ __forceinline__ float hsum2(u64 v) {
    float x, y; unpack2(v, x, y); return x + y;
}
__device__ __forceinline__ float tanha(float x) {
    float y; asm("tanh.approx.f32 %0,%1;" : "=f"(y) : "f"(x)); return y;
}

// ---------------------------------------------------------------------------
// R14 (RN/Z scalar chains) with the chain z-exchange moved to SHFL.
// Every warp spreads its 60 gate rows over 30 lanes with scalar FFMA:
//   lane i<20:    rows (r_i [prescaled 0.5], n_i)  -- r,n co-located; the
//                 serial r->tanh->n path never leaves the lane
//   lane 20+m<30: rows (z_2m, z_2m+1) [prescaled 0.5]
// In the CHAIN, z crosses lanes via two __shfl_sync (reading the z-lanes'
// registers) + SEL: ~26 cyc from value-ready, vs ~40+ for the smem round
// trip that made round 14 latency-bound. h rows still go through STS ->
// in-order LSU -> LDS.128 (feeds next step AND the GX1/head warps).
//
// gx layout per step: [60] floats (r 0..19 | z 20..39 | n 40..59), rows
// prescaled by the GX producers exactly as in round 13.
//
// Warp map (SMSP = w%4; chain warps at HIGH wid):
//   w0=GX0+xDMA+head(A) S0   w1=GX1(A) S1   w2=GX0+..(B) S2   w3=GX1(B) S3
//   w4=L0(A)            S0   w5=L1(A)  S1   w6=L0(B)     S2   w7=L1(B)  S3
// Lags: GX0 chunk c, L0 c-1, GX1 c-2, L1 c-3, head c-4. Rings 2-deep.
// sigmoid(s) = fma(tanh.approx(prescaled_sum), 0.5, 0.5).
// ---------------------------------------------------------------------------
__global__ void __launch_bounds__(256, 1)
fused_gru_kernel(const float* __restrict__ x,      // [B,T,C]
                 const float* __restrict__ h0in,   // [B,2,H]
                 const float* __restrict__ W_ih0, const float* __restrict__ W_hh0,
                 const float* __restrict__ b_ih0, const float* __restrict__ b_hh0,
                 const float* __restrict__ W_ih1, const float* __restrict__ W_hh1,
                 const float* __restrict__ b_ih1, const float* __restrict__ b_hh1,
                 const float* __restrict__ W_o,   const float* __restrict__ b_o,
                 float* __restrict__ out)          // o[B*T] then h_n[B,2,H]
{
    __shared__ __align__(16) float s_gx0[2][2][K][GG];  // 15 KB
    __shared__ __align__(16) float s_gx1[2][2][K][GG];  // 15 KB
    __shared__ __align__(16) float s_h0 [2][2][K][HH];  // 5 KB
    __shared__ __align__(16) float s_h1 [2][2][K][HH];  // 5 KB
    __shared__ __align__(16) float s_x  [2][2][K][CC];  // 4 KB

    const int tid = threadIdx.x;
    const int w   = tid >> 5;
    const int i   = tid & 31;
    const unsigned FULL = 0xFFFFFFFFu;

    const bool low  = (w < 4);
    const int bs    = low ? (w >> 1) : ((w - 4) >> 1);
    const int kind  = w & 1;   // low: 0=GX0+head 1=GX1 ; high: 0=L0 1=L1
    const int b     = blockIdx.x * 2 + bs;
    const float* xb = x + (size_t)b * TT * CC;

    // RN/Z lane -> (rowA, rowB, scales). Row index == gx slot index.
    const bool rn   = (i < HH);
    const bool zl   = (i >= HH) && (i < 30);
    const bool gxon = (i < 30);
    int rowA = 0, rowB = 0; float scA = 0.f, scB = 0.f;
    if (rn)      { rowA = i;                 scA = 0.5f; rowB = 2 * HH + i; scB = 1.0f; }
    else if (zl) { rowA = HH + 2 * (i - HH); scA = 0.5f; rowB = rowA + 1;   scB = 0.5f; }

    // ---- prime x chunk 0 (GX0 warps): 256 floats = 64 float4 ---------------
    if (low && kind == 0) {
        const float4* src = (const float4*)xb;
        float4* dst = (float4*)&s_x[bs][0][0][0];
        dst[i] = src[i]; dst[i + 32] = src[i + 32];
    }
    __syncthreads();

    if (low && kind == 0) {
        // ============ GX0 (scalar RN/Z) + x DMA + output head ================
        float wA[CC], wB[CC], bA = 0.f, bB = 0.f;
        u64 wo2[10];
#pragma unroll
        for (int c2 = 0; c2 < CC; ++c2) {
            wA[c2] = scA * W_ih0[rowA * CC + c2];
            wB[c2] = scB * W_ih0[rowB * CC + c2];
        }
        bA = scA * b_ih0[rowA]; bB = scB * b_ih0[rowB];
#pragma unroll
        for (int k = 0; k < 10; ++k)
            wo2[k] = pack2(W_o[2 * k], W_o[2 * k + 1]);
        const float bo = b_o[0];
        float* ob = out + (size_t)b * TT;

        for (int c = 0; c < NC + 4; ++c) {
            float4 pf0, pf1;
            const bool pf = (c + 1 < NC);
            if (pf) {
                const float4* src = (const float4*)(xb + (size_t)(c + 1) * K * CC);
                pf0 = src[i]; pf1 = src[i + 32];
            }
            if (c < NC) {
                const float* xs = &s_x[bs][c & 1][0][0];
                float* go = &s_gx0[bs][c & 1][0][0];
#pragma unroll 4
                for (int s = 0; s < K; ++s) {
                    const float4* x4 = (const float4*)(xs + s * CC);
                    float4 p0 = x4[0], p1 = x4[1], p2 = x4[2], p3 = x4[3];
                    float xf[CC] = {p0.x, p0.y, p0.z, p0.w, p1.x, p1.y, p1.z, p1.w,
                                    p2.x, p2.y, p2.z, p2.w, p3.x, p3.y, p3.z, p3.w};
                    float A0 = bA, A1 = 0.f, B0 = bB, B1 = 0.f;
#pragma unroll
                    for (int j = 0; j < CC; j += 2) {
                        A0 = fmaf(wA[j],     xf[j],     A0);
                        A1 = fmaf(wA[j + 1], xf[j + 1], A1);
                        B0 = fmaf(wB[j],     xf[j],     B0);
                        B1 = fmaf(wB[j + 1], xf[j + 1], B1);
                    }
                    if (gxon) {
                        go[s * GG + rowA] = A0 + A1;
                        go[s * GG + rowB] = B0 + B1;
                    }
                }
            }
            // output head for chunk c-4: lane l<K handles step l
            const int ch = c - 4;
            if (ch >= 0 && ch < NC && i < K) {
                const ulonglong2* hv2 = (const ulonglong2*)&s_h1[bs][ch & 1][i][0];
                ulonglong2 p0 = hv2[0], p1 = hv2[1], p2 = hv2[2], p3 = hv2[3], p4 = hv2[4];
                u64 hq[10] = {p0.x, p0.y, p1.x, p1.y, p2.x, p2.y, p3.x, p3.y, p4.x, p4.y};
                u64 acc = pack2(bo, 0.f);
#pragma unroll
                for (int k = 0; k < 10; ++k) fma2(acc, wo2[k], hq[k]);
                ob[ch * K + i] = hsum2(acc);
            }
            if (pf) {
                float4* dst = (float4*)&s_x[bs][(c + 1) & 1][0][0];
                dst[i] = pf0; dst[i + 32] = pf1;
            }
            __syncthreads();
        }
    } else if (low) {
        // ============ GX1 (scalar RN/Z): gx1 = W_ih1 . h0 ====================
        float wA[HH], wB[HH], bA = 0.f, bB = 0.f;
#pragma unroll
        for (int j = 0; j < HH; ++j) {
            wA[j] = scA * W_ih1[rowA * HH + j];
            wB[j] = scB * W_ih1[rowB * HH + j];
        }
        bA = scA * b_ih1[rowA]; bB = scB * b_ih1[rowB];

        for (int c = 0; c < NC + 4; ++c) {
            const int cg = c - 2;
            if (cg >= 0 && cg < NC) {
                const float* hr = &s_h0[bs][cg & 1][0][0];
                float* go = &s_gx1[bs][cg & 1][0][0];
#pragma unroll 4
                for (int s = 0; s < K; ++s) {
                    const float4* h4 = (const float4*)(hr + s * HH);
                    float4 p0 = h4[0], p1 = h4[1], p2 = h4[2], p3 = h4[3], p4 = h4[4];
                    float hf[HH] = {p0.x, p0.y, p0.z, p0.w, p1.x, p1.y, p1.z, p1.w,
                                    p2.x, p2.y, p2.z, p2.w, p3.x, p3.y, p3.z, p3.w,
                                    p4.x, p4.y, p4.z, p4.w};
                    float A0 = bA, A1 = 0.f, B0 = bB, B1 = 0.f;
#pragma unroll
                    for (int j = 0; j < HH; j += 2) {
                        A0 = fmaf(wA[j],     hf[j],     A0);
                        A1 = fmaf(wA[j + 1], hf[j + 1], A1);
                        B0 = fmaf(wB[j],     hf[j],     B0);
                        B1 = fmaf(wB[j + 1], hf[j + 1], B1);
                    }
                    if (gxon) {
                        go[s * GG + rowA] = A0 + A1;
                        go[s * GG + rowB] = B0 + B1;
                    }
                }
            }
            __syncthreads();
        }
    } else {
        // ============ L0 / L1: RN/Z scalar chains, z via SHFL ================
        const bool isL0  = (kind == 0);
        const float* Whh = isL0 ? W_hh0 : W_hh1;
        const float* bhh = isL0 ? b_hh0 : b_hh1;
        const int lag    = isL0 ? 1 : 3;
        const int layer  = kind;

        float wA[HH], wB[HH], bA = 0.f, bB = 0.f, h = 0.f;
#pragma unroll
        for (int j = 0; j < HH; ++j) {
            wA[j] = scA * Whh[rowA * HH + j];
            wB[j] = scB * Whh[rowB * HH + j];
        }
        bA = scA * bhh[rowA]; bB = scB * bhh[rowB];
        if (rn) h = h0in[(b * 2 + layer) * HH + i];

        // gx slot offsets for this lane
        const int oA = rn ? i : (zl ? HH + 2 * (i - HH) : 0);
        const int oB = rn ? (2 * HH + i) : (zl ? HH + 2 * (i - HH) + 1 : 0);
        // z shfl source lane for rn lanes: holder of pair (z_2m, z_2m+1)
        const int zsrc = rn ? (HH + (i >> 1)) : 31;

        // initial broadcast of h as scalars
        float hp[HH];
#pragma unroll
        for (int j = 0; j < HH; ++j)
            hp[j] = __shfl_sync(FULL, h, j);

        for (int c = 0; c < NC + 4; ++c) {
            const int cc = c - lag;
            if (cc >= 0 && cc < NC) {
                const float* gxp = isL0 ? &s_gx0[bs][cc & 1][0][0]
                                        : &s_gx1[bs][cc & 1][0][0];
                float* hw = isL0 ? &s_h0[bs][cc & 1][0][0]
                                 : &s_h1[bs][cc & 1][0][0];
#pragma unroll 2
                for (int s = 0; s < K; ++s) {
                    // gx for this lane (prescaled by producers)
                    const float gA = gxp[s * GG + oA];   // gr_i | gz_2m
                    const float gB = gxp[s * GG + oB];   // gn_i | gz_2m+1
                    // accumulators: fold gA into A; fold gB into B only for z
                    // lanes (n-gate: r multiplies the recurrent part only)
                    float A0 = bA + gA, A1 = 0.f;
                    float B0 = rn ? bB : (bB + gB), B1 = 0.f;
#pragma unroll
                    for (int j = 0; j < HH; j += 2) {
                        A0 = fmaf(wA[j],     hp[j],     A0);
                        A1 = fmaf(wA[j + 1], hp[j + 1], A1);
                        B0 = fmaf(wB[j],     hp[j],     B0);
                        B1 = fmaf(wB[j + 1], hp[j + 1], B1);
                    }
                    const float sumA = A0 + A1;
                    const float sumB = B0 + B1;
                    // first activation: r (rn lanes) | z_2m (z lanes)
                    const float u = fmaf(tanha(sumA), 0.5f, 0.5f);
                    // second: n = tanh(gn + r*rec) | tanh(pre_z1)
                    const float t2in = rn ? fmaf(u, sumB, gB) : sumB;
                    const float vB = tanha(t2in);
                    const float sigB = fmaf(vB, 0.5f, 0.5f);   // z-lanes: z_2m+1
                    // z transport via shfl (reads z-lanes' u / sigB registers)
                    const float zu = __shfl_sync(FULL, u,    zsrc);
                    const float zv = __shfl_sync(FULL, sigB, zsrc);
                    const float z  = (i & 1) ? zv : zu;
                    h = fmaf(z, h - vB, vB);          // rn lanes: n = vB
                    if (rn) hw[s * HH + i] = h;
                    asm volatile("" ::: "memory");
                    const float4* h4 = (const float4*)(hw + s * HH);
                    float4 q0 = h4[0], q1 = h4[1], q2 = h4[2], q3 = h4[3], q4 = h4[4];
                    hp[0] = q0.x; hp[1] = q0.y; hp[2] = q0.z; hp[3] = q0.w;
                    hp[4] = q1.x; hp[5] = q1.y; hp[6] = q1.z; hp[7] = q1.w;
                    hp[8] = q2.x; hp[9] = q2.y; hp[10] = q2.z; hp[11] = q2.w;
                    hp[12] = q3.x; hp[13] = q3.y; hp[14] = q3.z; hp[15] = q3.w;
                    hp[16] = q4.x; hp[17] = q4.y; hp[18] = q4.z; hp[19] = q4.w;
                }
            }
            __syncthreads();
        }
        if (rn) out[(size_t)BB * TT + (b * 2 + layer) * HH + i] = h;
    }
}

// ---------------------------------------------------------------------------
extern "C" void kernel_launch(void* const* d_in, const int* in_sizes, int n_in,
                              void* d_out, int out_size) {
    const float* x     = (const float*)d_in[0];
    const float* h0    = (const float*)d_in[1];
    const float* W_ih0 = (const float*)d_in[2];
    const float* W_hh0 = (const float*)d_in[3];
    const float* b_ih0 = (const float*)d_in[4];
    const float* b_hh0 = (const float*)d_in[5];
    const float* W_ih1 = (const float*)d_in[6];
    const float* W_hh1 = (const float*)d_in[7];
    const float* b_ih1 = (const float*)d_in[8];
    const float* b_hh1 = (const float*)d_in[9];
    const float* W_o   = (const float*)d_in[10];
    const float* b_o   = (const float*)d_in[11];

    fused_gru_kernel<<<BB / 2, 256>>>(x, h0, W_ih0, W_hh0, b_ih0, b_hh0,
                                      W_ih1, W_hh1, b_ih1, b_hh1, W_o, b_o,
                                      (float*)d_out);
}

// round 16
// speedup vs baseline: 1.0812x; 1.0812x over previous
#include <cuda_runtime.h>

// Fixed problem shape
#define BB 256
#define TT 4096
#define CC 16
#define HH 20
#define GG 60
#define K  16
#define NC (TT / K)   // 256 chunks

typedef unsigned long long u64;

__device__ __forceinline__ u64 pack2(float a, float b) {
    u64 r; asm("mov.b64 %0,{%1,%2};" : "=l"(r) : "f"(a), "f"(b)); return r;
}
__device__ __forceinline__ void unpack2(u64 v, float& a, float& b) {
    asm("mov.b64 {%0,%1},%2;" : "=f"(a), "=f"(b) : "l"(v));
}
__device__ __forceinline__ void fma2(u64& d, u64 a, u64 b) {
    asm("fma.rn.f32x2 %0,%1,%2,%0;" : "+l"(d) : "l"(a), "l"(b));
}
__device__ __forceinline__ float hsum2(u64 v) {
    float x, y; unpack2(v, x, y); return x + y;
}
__device__ __forceinline__ float tanha(float x) {
    float y; asm("tanh.approx.f32 %0,%1;" : "=f"(y) : "f"(x)); return y;
}
// Per-batch named barrier: 4 warps (128 threads) of one batch sync together.
__device__ __forceinline__ void batch_bar(int id) {
    asm volatile("bar.sync %0, 128;" :: "r"(id) : "memory");
}

// ---------------------------------------------------------------------------
// Round-13 architecture (best: 505.8 us) with two latency shavings:
//  1. chain h-exchange drops __syncwarp (same-warp STS -> LDS is processed
//     in order by the LSU; compiler barrier only) — saves ~23 cyc/step on
//     the serial recurrence path.
//  2. the two independent batches in a block sync on SEPARATE named barriers
//     (bar.sync 1 / bar.sync 2, 128 threads each) instead of one block-wide
//     __syncthreads — halves barrier width and decouples cross-batch skew.
//
// Warp map (SMSP = w%4; chain warps at HIGH wid):
//   w0=GX0+xDMA+head(A) S0   w1=GX1(A) S1   w2=GX0+..(B) S2   w3=GX1(B) S3
//   w4=L0(A)            S0   w5=L1(A)  S1   w6=L0(B)     S2   w7=L1(B)  S3
// Lags: GX0 chunk c, L0 c-1, GX1 c-2, L1 c-3, head c-4. Rings 2-deep.
// GX warps: scalar-FFMA RN/Z over 30 lanes (rows prescaled; gx layout
// [60] = r 0..19 | z 20..39 | n 40..59). Chains: 30 fma2, j-paired.
// sigmoid(s) = fma(tanh.approx(prescaled_sum), 0.5, 0.5).
// ---------------------------------------------------------------------------
__global__ void __launch_bounds__(256, 1)
fused_gru_kernel(const float* __restrict__ x,      // [B,T,C]
                 const float* __restrict__ h0in,   // [B,2,H]
                 const float* __restrict__ W_ih0, const float* __restrict__ W_hh0,
                 const float* __restrict__ b_ih0, const float* __restrict__ b_hh0,
                 const float* __restrict__ W_ih1, const float* __restrict__ W_hh1,
                 const float* __restrict__ b_ih1, const float* __restrict__ b_hh1,
                 const float* __restrict__ W_o,   const float* __restrict__ b_o,
                 float* __restrict__ out)          // o[B*T] then h_n[B,2,H]
{
    __shared__ __align__(16) float s_gx0[2][2][K][GG];  // 15 KB
    __shared__ __align__(16) float s_gx1[2][2][K][GG];  // 15 KB
    __shared__ __align__(16) float s_h0 [2][2][K][HH];  // 5 KB
    __shared__ __align__(16) float s_h1 [2][2][K][HH];  // 5 KB
    __shared__ __align__(16) float s_x  [2][2][K][CC];  // 4 KB

    const int tid = threadIdx.x;
    const int w   = tid >> 5;
    const int i   = tid & 31;
    const bool act = (i < HH);
    const unsigned FULL = 0xFFFFFFFFu;

    const bool low  = (w < 4);
    const int bs    = low ? (w >> 1) : ((w - 4) >> 1);
    const int kind  = w & 1;   // low: 0=GX0+head 1=GX1 ; high: 0=L0 1=L1
    const int bar   = bs + 1;  // named barrier id for this batch
    const int b     = blockIdx.x * 2 + bs;
    const float* xb = x + (size_t)b * TT * CC;

    // RN/Z lane -> (rowA, rowB, scales). Row index == gx slot index.
    const bool rn   = (i < HH);
    const bool zl   = (i >= HH) && (i < 30);
    const bool gxon = (i < 30);
    int rowA = 0, rowB = 0; float scA = 0.f, scB = 0.f;
    if (rn)      { rowA = i;                 scA = 0.5f; rowB = 2 * HH + i; scB = 1.0f; }
    else if (zl) { rowA = HH + 2 * (i - HH); scA = 0.5f; rowB = rowA + 1;   scB = 0.5f; }

    // ---- prime x chunk 0 (GX0 warps): 256 floats = 64 float4 ---------------
    if (low && kind == 0) {
        const float4* src = (const float4*)xb;
        float4* dst = (float4*)&s_x[bs][0][0][0];
        dst[i] = src[i]; dst[i + 32] = src[i + 32];
    }
    __syncthreads();

    if (low && kind == 0) {
        // ============ GX0 (scalar RN/Z) + x DMA + output head ================
        float wA[CC], wB[CC], bA = 0.f, bB = 0.f;
        u64 wo2[10];
#pragma unroll
        for (int c2 = 0; c2 < CC; ++c2) {
            wA[c2] = scA * W_ih0[rowA * CC + c2];
            wB[c2] = scB * W_ih0[rowB * CC + c2];
        }
        bA = scA * b_ih0[rowA]; bB = scB * b_ih0[rowB];
#pragma unroll
        for (int k = 0; k < 10; ++k)
            wo2[k] = pack2(W_o[2 * k], W_o[2 * k + 1]);
        const float bo = b_o[0];
        float* ob = out + (size_t)b * TT;

        for (int c = 0; c < NC + 4; ++c) {
            float4 pf0, pf1;
            const bool pf = (c + 1 < NC);
            if (pf) {
                const float4* src = (const float4*)(xb + (size_t)(c + 1) * K * CC);
                pf0 = src[i]; pf1 = src[i + 32];
            }
            if (c < NC) {
                const float* xs = &s_x[bs][c & 1][0][0];
                float* go = &s_gx0[bs][c & 1][0][0];
#pragma unroll 4
                for (int s = 0; s < K; ++s) {
                    const float4* x4 = (const float4*)(xs + s * CC);
                    float4 p0 = x4[0], p1 = x4[1], p2 = x4[2], p3 = x4[3];
                    float xf[CC] = {p0.x, p0.y, p0.z, p0.w, p1.x, p1.y, p1.z, p1.w,
                                    p2.x, p2.y, p2.z, p2.w, p3.x, p3.y, p3.z, p3.w};
                    float A0 = bA, A1 = 0.f, B0 = bB, B1 = 0.f;
#pragma unroll
                    for (int j = 0; j < CC; j += 2) {
                        A0 = fmaf(wA[j],     xf[j],     A0);
                        A1 = fmaf(wA[j + 1], xf[j + 1], A1);
                        B0 = fmaf(wB[j],     xf[j],     B0);
                        B1 = fmaf(wB[j + 1], xf[j + 1], B1);
                    }
                    if (gxon) {
                        go[s * GG + rowA] = A0 + A1;
                        go[s * GG + rowB] = B0 + B1;
                    }
                }
            }
            // output head for chunk c-4: lane l<K handles step l
            const int ch = c - 4;
            if (ch >= 0 && ch < NC && i < K) {
                const ulonglong2* hv2 = (const ulonglong2*)&s_h1[bs][ch & 1][i][0];
                ulonglong2 p0 = hv2[0], p1 = hv2[1], p2 = hv2[2], p3 = hv2[3], p4 = hv2[4];
                u64 hq[10] = {p0.x, p0.y, p1.x, p1.y, p2.x, p2.y, p3.x, p3.y, p4.x, p4.y};
                u64 acc = pack2(bo, 0.f);
#pragma unroll
                for (int k = 0; k < 10; ++k) fma2(acc, wo2[k], hq[k]);
                ob[ch * K + i] = hsum2(acc);
            }
            if (pf) {
                float4* dst = (float4*)&s_x[bs][(c + 1) & 1][0][0];
                dst[i] = pf0; dst[i + 32] = pf1;
            }
            batch_bar(bar);
        }
    } else if (low) {
        // ============ GX1 (scalar RN/Z): gx1 = W_ih1 . h0 ====================
        float wA[HH], wB[HH], bA = 0.f, bB = 0.f;
#pragma unroll
        for (int j = 0; j < HH; ++j) {
            wA[j] = scA * W_ih1[rowA * HH + j];
            wB[j] = scB * W_ih1[rowB * HH + j];
        }
        bA = scA * b_ih1[rowA]; bB = scB * b_ih1[rowB];

        for (int c = 0; c < NC + 4; ++c) {
            const int cg = c - 2;
            if (cg >= 0 && cg < NC) {
                const float* hr = &s_h0[bs][cg & 1][0][0];
                float* go = &s_gx1[bs][cg & 1][0][0];
#pragma unroll 4
                for (int s = 0; s < K; ++s) {
                    const float4* h4 = (const float4*)(hr + s * HH);
                    float4 p0 = h4[0], p1 = h4[1], p2 = h4[2], p3 = h4[3], p4 = h4[4];
                    float hf[HH] = {p0.x, p0.y, p0.z, p0.w, p1.x, p1.y, p1.z, p1.w,
                                    p2.x, p2.y, p2.z, p2.w, p3.x, p3.y, p3.z, p3.w,
                                    p4.x, p4.y, p4.z, p4.w};
                    float A0 = bA, A1 = 0.f, B0 = bB, B1 = 0.f;
#pragma unroll
                    for (int j = 0; j < HH; j += 2) {
                        A0 = fmaf(wA[j],     hf[j],     A0);
                        A1 = fmaf(wA[j + 1], hf[j + 1], A1);
                        B0 = fmaf(wB[j],     hf[j],     B0);
                        B1 = fmaf(wB[j + 1], hf[j + 1], B1);
                    }
                    if (gxon) {
                        go[s * GG + rowA] = A0 + A1;
                        go[s * GG + rowB] = B0 + B1;
                    }
                }
            }
            batch_bar(bar);
        }
    } else {
        // ============ L0 / L1: recurrence chains (round-9 form) ==============
        const bool isL0  = (kind == 0);
        const float* Whh = isL0 ? W_hh0 : W_hh1;
        const float* bhh = isL0 ? b_hh0 : b_hh1;
        const int lag    = isL0 ? 1 : 3;
        const int layer  = kind;

        u64 wh[30];
        float br = 0.f, bz = 0.f, bn = 0.f, h = 0.f;
#pragma unroll
        for (int g = 0; g < 3; ++g) {
            const float sc = (g < 2) ? 0.5f : 1.0f;
#pragma unroll
            for (int k = 0; k < 10; ++k)
                wh[g * 10 + k] = act ? pack2(sc * Whh[(g * HH + i) * HH + 2 * k],
                                             sc * Whh[(g * HH + i) * HH + 2 * k + 1])
                                     : pack2(0.f, 0.f);
        }
        if (act) {
            br = 0.5f * bhh[i]; bz = 0.5f * bhh[HH + i]; bn = bhh[2 * HH + i];
            h = h0in[(b * 2 + layer) * HH + i];
        }

        // initial broadcast of h (once)
        u64 hp[10];
#pragma unroll
        for (int k = 0; k < 10; ++k)
            hp[k] = pack2(__shfl_sync(FULL, h, 2 * k),
                          __shfl_sync(FULL, h, 2 * k + 1));

        for (int c = 0; c < NC + 4; ++c) {
            const int cc = c - lag;
            if (cc >= 0 && cc < NC) {
                const float* gxp = isL0 ? &s_gx0[bs][cc & 1][0][0]
                                        : &s_gx1[bs][cc & 1][0][0];
                float* hw = isL0 ? &s_h0[bs][cc & 1][0][0]
                                 : &s_h1[bs][cc & 1][0][0];
#pragma unroll 2
                for (int s = 0; s < K; ++s) {
                    float gr = 0.f, gz = 0.f, gn = 0.f;
                    if (act) {
                        gr = gxp[s * GG + i];
                        gz = gxp[s * GG + HH + i];
                        gn = gxp[s * GG + 2 * HH + i];
                    }
                    // gate dots, grouped so r completes earliest
                    u64 ar = pack2(br, 0.f);
#pragma unroll
                    for (int k = 0; k < 10; ++k) fma2(ar, wh[k], hp[k]);
                    u64 az = pack2(bz, 0.f);
#pragma unroll
                    for (int k = 0; k < 10; ++k) fma2(az, wh[10 + k], hp[k]);
                    u64 an = pack2(bn, 0.f);
#pragma unroll
                    for (int k = 0; k < 10; ++k) fma2(an, wh[20 + k], hp[k]);

                    const float r = fmaf(tanha(gr + hsum2(ar)), 0.5f, 0.5f);
                    const float z = fmaf(tanha(gz + hsum2(az)), 0.5f, 0.5f);
                    const float n = tanha(fmaf(r, hsum2(an), gn));
                    h = fmaf(z, h - n, n);

                    // exchange h through the s_h row (also feeds GX1/head):
                    // same-warp STS -> LDS is processed in order by the LSU;
                    // compiler barrier only (no WARPSYNC on the serial path).
                    if (act) hw[s * HH + i] = h;
                    asm volatile("" ::: "memory");
                    const ulonglong2* hv2 = (const ulonglong2*)(hw + s * HH);
                    ulonglong2 p0 = hv2[0], p1 = hv2[1], p2 = hv2[2], p3 = hv2[3], p4 = hv2[4];
                    hp[0] = p0.x; hp[1] = p0.y; hp[2] = p1.x; hp[3] = p1.y;
                    hp[4] = p2.x; hp[5] = p2.y; hp[6] = p3.x; hp[7] = p3.y;
                    hp[8] = p4.x; hp[9] = p4.y;
                }
            }
            batch_bar(bar);
        }
        if (act) out[(size_t)BB * TT + (b * 2 + layer) * HH + i] = h;
    }
}

// ---------------------------------------------------------------------------
extern "C" void kernel_launch(void* const* d_in, const int* in_sizes, int n_in,
                              void* d_out, int out_size) {
    const float* x     = (const float*)d_in[0];
    const float* h0    = (const float*)d_in[1];
    const float* W_ih0 = (const float*)d_in[2];
    const float* W_hh0 = (const float*)d_in[3];
    const float* b_ih0 = (const float*)d_in[4];
    const float* b_hh0 = (const float*)d_in[5];
    const float* W_ih1 = (const float*)d_in[6];
    const float* W_hh1 = (const float*)d_in[7];
    const float* b_ih1 = (const float*)d_in[8];
    const float* b_hh1 = (const float*)d_in[9];
    const float* W_o   = (const float*)d_in[10];
    const float* b_o   = (const float*)d_in[11];

    fused_gru_kernel<<<BB / 2, 256>>>(x, h0, W_ih0, W_hh0, b_ih0, b_hh0,
                                      W_ih1, W_hh1, b_ih1, b_hh1, W_o, b_o,
                                      (float*)d_out);
}